// round 2
// baseline (speedup 1.0000x reference)
#include <cuda_runtime.h>
#include <math.h>

// Problem constants
#define BB 2
#define SS 2048
#define DD 2048
#define NH 32
#define NKV 8
#define HD 64
#define GG 4   // NH / NKV

// Scratch buffers (static device globals; no allocation allowed)
__device__ float g_Q[BB * SS * NH * HD];    // (b, s, h, d)
__device__ float g_K[BB * SS * NKV * HD];   // (b, s, kh, d)
__device__ float g_V[BB * SS * NKV * HD];
__device__ float g_O[BB * SS * NH * HD];    // attention output, (b, s, h, d)

// ---------------------------------------------------------------------------
// SGEMM: C[M,N] = A[M,K] @ B[N,K]^T + bias[N]
// BM=BN=128, BK=8, 256 threads, 8x8 per-thread tile.
// Requires M%128==0, N%128==0, K%8==0 (true for all our shapes).
// ---------------------------------------------------------------------------
__global__ __launch_bounds__(256, 2)
void sgemm_bias(const float* __restrict__ A, const float* __restrict__ B,
                const float* __restrict__ bias, float* __restrict__ C,
                int M, int N, int K) {
    __shared__ float As[8][128];
    __shared__ float Bs[8][128];

    const int t = threadIdx.x;
    const int m0 = blockIdx.y * 128;
    const int n0 = blockIdx.x * 128;

    const int lrow = t >> 1;          // 0..127
    const int lc4  = (t & 1) * 4;     // 0 or 4

    const int tr = t >> 4;            // 0..15
    const int tc = t & 15;            // 0..15

    float acc[8][8];
#pragma unroll
    for (int i = 0; i < 8; i++)
#pragma unroll
        for (int j = 0; j < 8; j++) acc[i][j] = 0.f;

    const float* Ap = A + (size_t)(m0 + lrow) * K + lc4;
    const float* Bp = B + (size_t)(n0 + lrow) * K + lc4;

    for (int k0 = 0; k0 < K; k0 += 8) {
        float4 av = *(const float4*)(Ap + k0);
        float4 bv = *(const float4*)(Bp + k0);
        __syncthreads();
        As[lc4 + 0][lrow] = av.x; As[lc4 + 1][lrow] = av.y;
        As[lc4 + 2][lrow] = av.z; As[lc4 + 3][lrow] = av.w;
        Bs[lc4 + 0][lrow] = bv.x; Bs[lc4 + 1][lrow] = bv.y;
        Bs[lc4 + 2][lrow] = bv.z; Bs[lc4 + 3][lrow] = bv.w;
        __syncthreads();

#pragma unroll
        for (int k = 0; k < 8; k++) {
            float4 a0 = *(const float4*)&As[k][tr * 8];
            float4 a1 = *(const float4*)&As[k][tr * 8 + 4];
            float4 b0 = *(const float4*)&Bs[k][tc * 8];
            float4 b1 = *(const float4*)&Bs[k][tc * 8 + 4];
            float ar[8] = {a0.x, a0.y, a0.z, a0.w, a1.x, a1.y, a1.z, a1.w};
            float br[8] = {b0.x, b0.y, b0.z, b0.w, b1.x, b1.y, b1.z, b1.w};
#pragma unroll
            for (int i = 0; i < 8; i++)
#pragma unroll
                for (int j = 0; j < 8; j++) acc[i][j] += ar[i] * br[j];
        }
    }

    // Epilogue with bias
#pragma unroll
    for (int i = 0; i < 8; i++) {
        float* Cp = C + (size_t)(m0 + tr * 8 + i) * N + n0 + tc * 8;
        const float* bp = bias + n0 + tc * 8;
        float4 r0, r1;
        r0.x = acc[i][0] + bp[0]; r0.y = acc[i][1] + bp[1];
        r0.z = acc[i][2] + bp[2]; r0.w = acc[i][3] + bp[3];
        r1.x = acc[i][4] + bp[4]; r1.y = acc[i][5] + bp[5];
        r1.z = acc[i][6] + bp[6]; r1.w = acc[i][7] + bp[7];
        *(float4*)(Cp) = r0;
        *(float4*)(Cp + 4) = r1;
    }
}

// ---------------------------------------------------------------------------
// Flash attention (causal, GQA). 64x64 tiles, fp32.
// grid: (S/64, NH, B), block: 256 threads.
// Q/O layout: (b, s, h, d) ; K/V layout: (b, s, kh, d)
// ---------------------------------------------------------------------------
#define FA_STRIDE 68   // padded row stride in shared memory (floats)

__global__ __launch_bounds__(256, 2)
void flash_attn(const float* __restrict__ Q, const float* __restrict__ Kb,
                const float* __restrict__ Vb, float* __restrict__ O) {
    const int qt = blockIdx.x;
    const int h  = blockIdx.y;
    const int b  = blockIdx.z;
    const int kh = h >> 2;         // GG = 4
    const int q0 = qt * 64;

    const int t  = threadIdx.x;
    const int tr = t >> 4;         // 0..15 -> rows tr*4..tr*4+3
    const int tc = t & 15;         // 0..15 -> cols tc*4..tc*4+3

    extern __shared__ float sm[];
    float* Qs = sm;
    float* Ks = sm + 64 * FA_STRIDE;
    float* Vs = sm + 2 * 64 * FA_STRIDE;
    float* Ps = sm + 3 * 64 * FA_STRIDE;

    // Load Q tile (64 rows x 64 d)
    const float* Qg = Q + ((size_t)(b * SS + q0) * NH + h) * HD;
#pragma unroll
    for (int i = 0; i < 4; i++) {
        int idx = i * 256 + t;
        int r = idx >> 4;
        int c4 = (idx & 15) * 4;
        *(float4*)(Qs + r * FA_STRIDE + c4) =
            *(const float4*)(Qg + (size_t)r * (NH * HD) + c4);
    }

    const float* Kg = Kb + ((size_t)(b * SS) * NKV + kh) * HD;
    const float* Vg = Vb + ((size_t)(b * SS) * NKV + kh) * HD;

    float o[4][4];
    float mr[4], lr[4];
#pragma unroll
    for (int i = 0; i < 4; i++) {
        mr[i] = -1e30f;
        lr[i] = 0.f;
#pragma unroll
        for (int j = 0; j < 4; j++) o[i][j] = 0.f;
    }

    for (int kt = 0; kt <= qt; kt++) {
        const int k0 = kt * 64;
        __syncthreads();   // previous PV done; Q visible on first iter
#pragma unroll
        for (int i = 0; i < 4; i++) {
            int idx = i * 256 + t;
            int r = idx >> 4;
            int c4 = (idx & 15) * 4;
            *(float4*)(Ks + r * FA_STRIDE + c4) =
                *(const float4*)(Kg + (size_t)(k0 + r) * (NKV * HD) + c4);
            *(float4*)(Vs + r * FA_STRIDE + c4) =
                *(const float4*)(Vg + (size_t)(k0 + r) * (NKV * HD) + c4);
        }
        __syncthreads();

        // Scores: s[i][j] = Q[tr*4+i] . K[tc*4+j]
        float s[4][4];
#pragma unroll
        for (int i = 0; i < 4; i++)
#pragma unroll
            for (int j = 0; j < 4; j++) s[i][j] = 0.f;

#pragma unroll
        for (int d4 = 0; d4 < 16; d4++) {
            float4 qv[4], kv[4];
#pragma unroll
            for (int i = 0; i < 4; i++)
                qv[i] = *(const float4*)(Qs + (tr * 4 + i) * FA_STRIDE + d4 * 4);
#pragma unroll
            for (int j = 0; j < 4; j++)
                kv[j] = *(const float4*)(Ks + (tc * 4 + j) * FA_STRIDE + d4 * 4);
#pragma unroll
            for (int i = 0; i < 4; i++)
#pragma unroll
                for (int j = 0; j < 4; j++) {
                    s[i][j] += qv[i].x * kv[j].x + qv[i].y * kv[j].y +
                               qv[i].z * kv[j].z + qv[i].w * kv[j].w;
                }
        }

        // scale + causal mask (only diagonal tile needs masking)
        const float scale = 0.125f;  // 1/sqrt(64)
#pragma unroll
        for (int i = 0; i < 4; i++)
#pragma unroll
            for (int j = 0; j < 4; j++) {
                s[i][j] *= scale;
                if (kt == qt && (tc * 4 + j) > (tr * 4 + i)) s[i][j] = -1e30f;
            }

        // row max over this tile (reduce across 16 threads sharing rows)
        float rm[4];
#pragma unroll
        for (int i = 0; i < 4; i++) {
            rm[i] = fmaxf(fmaxf(s[i][0], s[i][1]), fmaxf(s[i][2], s[i][3]));
        }
#pragma unroll
        for (int off = 8; off >= 1; off >>= 1) {
#pragma unroll
            for (int i = 0; i < 4; i++)
                rm[i] = fmaxf(rm[i], __shfl_xor_sync(0xffffffffu, rm[i], off));
        }

        float al[4];
#pragma unroll
        for (int i = 0; i < 4; i++) {
            float mn = fmaxf(mr[i], rm[i]);
            al[i] = __expf(mr[i] - mn);
            mr[i] = mn;
        }

        // p = exp(s - m), row sum
        float rs[4];
#pragma unroll
        for (int i = 0; i < 4; i++) {
            float su = 0.f;
#pragma unroll
            for (int j = 0; j < 4; j++) {
                s[i][j] = __expf(s[i][j] - mr[i]);
                su += s[i][j];
            }
            rs[i] = su;
        }
#pragma unroll
        for (int off = 8; off >= 1; off >>= 1) {
#pragma unroll
            for (int i = 0; i < 4; i++)
                rs[i] += __shfl_xor_sync(0xffffffffu, rs[i], off);
        }

#pragma unroll
        for (int i = 0; i < 4; i++) {
            lr[i] = lr[i] * al[i] + rs[i];
#pragma unroll
            for (int j = 0; j < 4; j++) o[i][j] *= al[i];
            // store P row chunk
            float4 pv = make_float4(s[i][0], s[i][1], s[i][2], s[i][3]);
            *(float4*)(Ps + (tr * 4 + i) * FA_STRIDE + tc * 4) = pv;
        }
        __syncthreads();

        // O += P @ V   (rows tr*4.., d-cols tc*4..)
#pragma unroll 4
        for (int c = 0; c < 64; c++) {
            float4 vv = *(const float4*)(Vs + c * FA_STRIDE + tc * 4);
#pragma unroll
            for (int i = 0; i < 4; i++) {
                float p = Ps[(tr * 4 + i) * FA_STRIDE + c];
                o[i][0] += p * vv.x;
                o[i][1] += p * vv.y;
                o[i][2] += p * vv.z;
                o[i][3] += p * vv.w;
            }
        }
    }

    // finalize + store
#pragma unroll
    for (int i = 0; i < 4; i++) {
        float inv = 1.f / lr[i];
        float4 r;
        r.x = o[i][0] * inv; r.y = o[i][1] * inv;
        r.z = o[i][2] * inv; r.w = o[i][3] * inv;
        float* Og = O + ((size_t)(b * SS + q0 + tr * 4 + i) * NH + h) * HD + tc * 4;
        *(float4*)Og = r;
    }
}

// ---------------------------------------------------------------------------
extern "C" void kernel_launch(void* const* d_in, const int* in_sizes, int n_in,
                              void* d_out, int out_size) {
    (void)in_sizes; (void)n_in; (void)out_size;
    const float* x  = (const float*)d_in[0];
    const float* wq = (const float*)d_in[1];
    const float* bq = (const float*)d_in[2];
    const float* wk = (const float*)d_in[3];
    const float* bk = (const float*)d_in[4];
    const float* wv = (const float*)d_in[5];
    const float* bv = (const float*)d_in[6];
    const float* wo = (const float*)d_in[7];
    const float* bo = (const float*)d_in[8];
    float* out = (float*)d_out;

    float *qb, *kb, *vb, *ob;
    cudaGetSymbolAddress((void**)&qb, g_Q);
    cudaGetSymbolAddress((void**)&kb, g_K);
    cudaGetSymbolAddress((void**)&vb, g_V);
    cudaGetSymbolAddress((void**)&ob, g_O);

    const int M = BB * SS;           // 4096
    const size_t smem = 4 * 64 * FA_STRIDE * sizeof(float);  // 69632 B
    cudaFuncSetAttribute(flash_attn, cudaFuncAttributeMaxDynamicSharedMemorySize,
                         (int)smem);

    // Q, K, V projections
    dim3 gq(DD / 128, M / 128);                  // (16, 32)
    sgemm_bias<<<gq, 256>>>(x, wq, bq, qb, M, NH * HD, DD);
    dim3 gk((NKV * HD) / 128, M / 128);          // (4, 32)
    sgemm_bias<<<gk, 256>>>(x, wk, bk, kb, M, NKV * HD, DD);
    sgemm_bias<<<gk, 256>>>(x, wv, bv, vb, M, NKV * HD, DD);

    // Flash attention
    dim3 gf(SS / 64, NH, BB);                    // (32, 32, 2)
    flash_attn<<<gf, 256, smem>>>(qb, kb, vb, ob);

    // Output projection
    sgemm_bias<<<gq, 256>>>(ob, wo, bo, out, M, DD, NH * HD);
}

// round 4
// speedup vs baseline: 1.4554x; 1.4554x over previous
#include <cuda_runtime.h>
#include <cuda_bf16.h>
#include <math.h>
#include <stdint.h>

// Problem constants
#define BB 2
#define SS 2048
#define DD 2048
#define NH 32
#define NKV 8
#define HD 64
#define GG 4   // NH / NKV

#define GKP 6144          // split-K: 3 x 2048
#define NCHUNK 192        // 6144 / 32

// ---------------------------------------------------------------------------
// Scratch buffers (static device globals; no allocation allowed)
// ---------------------------------------------------------------------------
__device__ float g_Q[BB * SS * NH * HD];    // [4096, 2048]
__device__ float g_K[BB * SS * NKV * HD];   // [4096, 512]
__device__ float g_V[BB * SS * NKV * HD];
__device__ float g_O[BB * SS * NH * HD];

__device__ __nv_bfloat16 g_xs[BB * SS * GKP];        // x split   (hi,hi,lo)
__device__ __nv_bfloat16 g_os[BB * SS * GKP];        // attn out split (hi,hi,lo)
__device__ __nv_bfloat16 g_wqs[(NH * HD) * GKP];     // w split   (hi,lo,hi)
__device__ __nv_bfloat16 g_wks[(NKV * HD) * GKP];
__device__ __nv_bfloat16 g_wvs[(NKV * HD) * GKP];
__device__ __nv_bfloat16 g_wos[DD * GKP];

// ---------------------------------------------------------------------------
__device__ __forceinline__ uint32_t smem_u32(const void* p) {
    uint32_t a;
    asm("{ .reg .u64 t; cvta.to.shared.u64 t, %1; cvt.u32.u64 %0, t; }"
        : "=r"(a) : "l"(p));
    return a;
}

// ---------------------------------------------------------------------------
// Split kernels: fp32 [rows,2048] -> bf16 [rows,6144]
// ---------------------------------------------------------------------------
__global__ void split_hhl(const float* __restrict__ in,
                          __nv_bfloat16* __restrict__ out, int rows) {
    int idx = blockIdx.x * 256 + threadIdx.x;
    if (idx >= rows * 2048) return;
    int r = idx >> 11, c = idx & 2047;
    float v = in[idx];
    __nv_bfloat16 h = __float2bfloat16(v);
    __nv_bfloat16 l = __float2bfloat16(v - __bfloat162float(h));
    size_t o = (size_t)r * GKP + c;
    out[o] = h; out[o + 2048] = h; out[o + 4096] = l;
}

__global__ void split_hlh(const float* __restrict__ in,
                          __nv_bfloat16* __restrict__ out, int rows) {
    int idx = blockIdx.x * 256 + threadIdx.x;
    if (idx >= rows * 2048) return;
    int r = idx >> 11, c = idx & 2047;
    float v = in[idx];
    __nv_bfloat16 h = __float2bfloat16(v);
    __nv_bfloat16 l = __float2bfloat16(v - __bfloat162float(h));
    size_t o = (size_t)r * GKP + c;
    out[o] = h; out[o + 2048] = l; out[o + 4096] = h;
}

// ---------------------------------------------------------------------------
// bf16 warp-MMA GEMM: C[m][n] = sum_k A[m][k]*B[n][k] + bias[n]
// A: [M, 6144] bf16 rm, B: [N, 6144] bf16 rm, C fp32 [M, N]
// Tile 128x128x32, 256 threads (8 warps, 2x4), warp tile 64x32.
// smem rows padded to 40 bf16 (80 B) -> conflict-free ldmatrix.
// ---------------------------------------------------------------------------
#define SKW_B 80                 // bytes per smem row
#define A_TILE_B (128 * SKW_B)   // 10240
#define STAGE_B  (2 * A_TILE_B)  // 20480 (A + B)
#define GEMM_SMEM (2 * STAGE_B)  // 40960

__global__ __launch_bounds__(256, 2)
void gemm_mma(const __nv_bfloat16* __restrict__ A,
              const __nv_bfloat16* __restrict__ Bm,
              const float* __restrict__ bias,
              float* __restrict__ C, int N) {
    extern __shared__ __align__(128) char smem[];
    const uint32_t sb = smem_u32(smem);
    const int t = threadIdx.x;
    const int wid = t >> 5;
    const int lane = t & 31;
    const int wm = wid & 1;      // 0..1  (M)
    const int wn = wid >> 1;     // 0..3  (N)
    const int m0 = blockIdx.y * 128;
    const int n0 = blockIdx.x * 128;

    // per-thread cp.async map: 2 segments of 16B for A and B each
    uint32_t soff[2];
    const __nv_bfloat16* ag[2];
    const __nv_bfloat16* bg[2];
#pragma unroll
    for (int i = 0; i < 2; i++) {
        int s = t + 256 * i;
        int r = s >> 2, sg = s & 3;
        soff[i] = (uint32_t)(r * SKW_B + sg * 16);
        ag[i] = A + (size_t)(m0 + r) * GKP + sg * 8;
        bg[i] = Bm + (size_t)(n0 + r) * GKP + sg * 8;
    }

    // ldmatrix address components
    const int aRow = (lane & 7) + (lane & 8);          // 0..15
    const uint32_t aColB = (lane & 16) ? 16u : 0u;     // byte offset in k
    const int bRow = (lane & 7) + ((lane & 16) ? 8 : 0);
    const uint32_t bColB = (lane & 8) ? 16u : 0u;

    float acc[4][4][4];
#pragma unroll
    for (int i = 0; i < 4; i++)
#pragma unroll
        for (int j = 0; j < 4; j++)
#pragma unroll
            for (int r = 0; r < 4; r++) acc[i][j][r] = 0.f;

    // prologue: stage 0
#pragma unroll
    for (int i = 0; i < 2; i++) {
        asm volatile("cp.async.cg.shared.global [%0], [%1], 16;"
                     :: "r"(sb + soff[i]), "l"((const void*)ag[i]));
        asm volatile("cp.async.cg.shared.global [%0], [%1], 16;"
                     :: "r"(sb + A_TILE_B + soff[i]), "l"((const void*)bg[i]));
    }
    asm volatile("cp.async.commit_group;");

    for (int ch = 0; ch < NCHUNK; ch++) {
        if (ch + 1 < NCHUNK) {
            const uint32_t st = ((ch + 1) & 1) ? STAGE_B : 0u;
            const int ko = (ch + 1) * 32;
#pragma unroll
            for (int i = 0; i < 2; i++) {
                asm volatile("cp.async.cg.shared.global [%0], [%1], 16;"
                             :: "r"(sb + st + soff[i]), "l"((const void*)(ag[i] + ko)));
                asm volatile("cp.async.cg.shared.global [%0], [%1], 16;"
                             :: "r"(sb + st + A_TILE_B + soff[i]), "l"((const void*)(bg[i] + ko)));
            }
            asm volatile("cp.async.commit_group;");
            asm volatile("cp.async.wait_group 1;");
        } else {
            asm volatile("cp.async.wait_group 0;");
        }
        __syncthreads();

        const uint32_t Ab = sb + ((ch & 1) ? STAGE_B : 0u);
        const uint32_t Bb = Ab + A_TILE_B;
        const uint32_t aBase = Ab + (uint32_t)(wm * 64 + aRow) * SKW_B + aColB;
        const uint32_t bBase = Bb + (uint32_t)(wn * 32 + bRow) * SKW_B + bColB;

#pragma unroll
        for (int ks = 0; ks < 2; ks++) {
            uint32_t a[4][4];
            uint32_t b[4][2];
#pragma unroll
            for (int i = 0; i < 4; i++) {
                uint32_t ad = aBase + (uint32_t)(i * 16) * SKW_B + ks * 32;
                asm volatile(
                    "ldmatrix.sync.aligned.m8n8.x4.shared.b16 {%0,%1,%2,%3}, [%4];"
                    : "=r"(a[i][0]), "=r"(a[i][1]), "=r"(a[i][2]), "=r"(a[i][3])
                    : "r"(ad));
            }
#pragma unroll
            for (int j2 = 0; j2 < 2; j2++) {
                uint32_t bd = bBase + (uint32_t)(j2 * 16) * SKW_B + ks * 32;
                asm volatile(
                    "ldmatrix.sync.aligned.m8n8.x4.shared.b16 {%0,%1,%2,%3}, [%4];"
                    : "=r"(b[2 * j2][0]), "=r"(b[2 * j2][1]),
                      "=r"(b[2 * j2 + 1][0]), "=r"(b[2 * j2 + 1][1])
                    : "r"(bd));
            }
#pragma unroll
            for (int i = 0; i < 4; i++)
#pragma unroll
                for (int j = 0; j < 4; j++) {
                    asm volatile(
                        "mma.sync.aligned.m16n8k16.row.col.f32.bf16.bf16.f32 "
                        "{%0,%1,%2,%3}, {%4,%5,%6,%7}, {%8,%9}, {%0,%1,%2,%3};"
                        : "+f"(acc[i][j][0]), "+f"(acc[i][j][1]),
                          "+f"(acc[i][j][2]), "+f"(acc[i][j][3])
                        : "r"(a[i][0]), "r"(a[i][1]), "r"(a[i][2]), "r"(a[i][3]),
                          "r"(b[j][0]), "r"(b[j][1]));
                }
        }
        __syncthreads();
    }

    // Epilogue: acc layout -> C rows (lane>>2, +8), cols (lane&3)*2 (+1)
#pragma unroll
    for (int i = 0; i < 4; i++) {
        const int r0 = m0 + wm * 64 + i * 16 + (lane >> 2);
#pragma unroll
        for (int j = 0; j < 4; j++) {
            const int c = n0 + wn * 32 + j * 8 + (lane & 3) * 2;
            const float b0 = bias[c], b1 = bias[c + 1];
            float2 v0 = make_float2(acc[i][j][0] + b0, acc[i][j][1] + b1);
            float2 v1 = make_float2(acc[i][j][2] + b0, acc[i][j][3] + b1);
            *(float2*)(C + (size_t)r0 * N + c) = v0;
            *(float2*)(C + (size_t)(r0 + 8) * N + c) = v1;
        }
    }
}

// ---------------------------------------------------------------------------
// Flash attention (causal, GQA). 64x64 tiles, fp32. (unchanged)
// ---------------------------------------------------------------------------
#define FA_STRIDE 68

__global__ __launch_bounds__(256, 2)
void flash_attn(const float* __restrict__ Q, const float* __restrict__ Kb,
                const float* __restrict__ Vb, float* __restrict__ O) {
    const int qt = blockIdx.x;
    const int h  = blockIdx.y;
    const int b  = blockIdx.z;
    const int kh = h >> 2;
    const int q0 = qt * 64;

    const int t  = threadIdx.x;
    const int tr = t >> 4;
    const int tc = t & 15;

    extern __shared__ float sm[];
    float* Qs = sm;
    float* Ks = sm + 64 * FA_STRIDE;
    float* Vs = sm + 2 * 64 * FA_STRIDE;
    float* Ps = sm + 3 * 64 * FA_STRIDE;

    const float* Qg = Q + ((size_t)(b * SS + q0) * NH + h) * HD;
#pragma unroll
    for (int i = 0; i < 4; i++) {
        int idx = i * 256 + t;
        int r = idx >> 4;
        int c4 = (idx & 15) * 4;
        *(float4*)(Qs + r * FA_STRIDE + c4) =
            *(const float4*)(Qg + (size_t)r * (NH * HD) + c4);
    }

    const float* Kg = Kb + ((size_t)(b * SS) * NKV + kh) * HD;
    const float* Vg = Vb + ((size_t)(b * SS) * NKV + kh) * HD;

    float o[4][4];
    float mr[4], lr[4];
#pragma unroll
    for (int i = 0; i < 4; i++) {
        mr[i] = -1e30f;
        lr[i] = 0.f;
#pragma unroll
        for (int j = 0; j < 4; j++) o[i][j] = 0.f;
    }

    for (int kt = 0; kt <= qt; kt++) {
        const int k0 = kt * 64;
        __syncthreads();
#pragma unroll
        for (int i = 0; i < 4; i++) {
            int idx = i * 256 + t;
            int r = idx >> 4;
            int c4 = (idx & 15) * 4;
            *(float4*)(Ks + r * FA_STRIDE + c4) =
                *(const float4*)(Kg + (size_t)(k0 + r) * (NKV * HD) + c4);
            *(float4*)(Vs + r * FA_STRIDE + c4) =
                *(const float4*)(Vg + (size_t)(k0 + r) * (NKV * HD) + c4);
        }
        __syncthreads();

        float s[4][4];
#pragma unroll
        for (int i = 0; i < 4; i++)
#pragma unroll
            for (int j = 0; j < 4; j++) s[i][j] = 0.f;

#pragma unroll
        for (int d4 = 0; d4 < 16; d4++) {
            float4 qv[4], kv[4];
#pragma unroll
            for (int i = 0; i < 4; i++)
                qv[i] = *(const float4*)(Qs + (tr * 4 + i) * FA_STRIDE + d4 * 4);
#pragma unroll
            for (int j = 0; j < 4; j++)
                kv[j] = *(const float4*)(Ks + (tc * 4 + j) * FA_STRIDE + d4 * 4);
#pragma unroll
            for (int i = 0; i < 4; i++)
#pragma unroll
                for (int j = 0; j < 4; j++) {
                    s[i][j] += qv[i].x * kv[j].x + qv[i].y * kv[j].y +
                               qv[i].z * kv[j].z + qv[i].w * kv[j].w;
                }
        }

        const float scale = 0.125f;
#pragma unroll
        for (int i = 0; i < 4; i++)
#pragma unroll
            for (int j = 0; j < 4; j++) {
                s[i][j] *= scale;
                if (kt == qt && (tc * 4 + j) > (tr * 4 + i)) s[i][j] = -1e30f;
            }

        float rm[4];
#pragma unroll
        for (int i = 0; i < 4; i++)
            rm[i] = fmaxf(fmaxf(s[i][0], s[i][1]), fmaxf(s[i][2], s[i][3]));
#pragma unroll
        for (int off = 8; off >= 1; off >>= 1) {
#pragma unroll
            for (int i = 0; i < 4; i++)
                rm[i] = fmaxf(rm[i], __shfl_xor_sync(0xffffffffu, rm[i], off));
        }

        float al[4];
#pragma unroll
        for (int i = 0; i < 4; i++) {
            float mn = fmaxf(mr[i], rm[i]);
            al[i] = __expf(mr[i] - mn);
            mr[i] = mn;
        }

        float rs[4];
#pragma unroll
        for (int i = 0; i < 4; i++) {
            float su = 0.f;
#pragma unroll
            for (int j = 0; j < 4; j++) {
                s[i][j] = __expf(s[i][j] - mr[i]);
                su += s[i][j];
            }
            rs[i] = su;
        }
#pragma unroll
        for (int off = 8; off >= 1; off >>= 1) {
#pragma unroll
            for (int i = 0; i < 4; i++)
                rs[i] += __shfl_xor_sync(0xffffffffu, rs[i], off);
        }

#pragma unroll
        for (int i = 0; i < 4; i++) {
            lr[i] = lr[i] * al[i] + rs[i];
#pragma unroll
            for (int j = 0; j < 4; j++) o[i][j] *= al[i];
            float4 pv = make_float4(s[i][0], s[i][1], s[i][2], s[i][3]);
            *(float4*)(Ps + (tr * 4 + i) * FA_STRIDE + tc * 4) = pv;
        }
        __syncthreads();

#pragma unroll 4
        for (int c = 0; c < 64; c++) {
            float4 vv = *(const float4*)(Vs + c * FA_STRIDE + tc * 4);
#pragma unroll
            for (int i = 0; i < 4; i++) {
                float p = Ps[(tr * 4 + i) * FA_STRIDE + c];
                o[i][0] += p * vv.x;
                o[i][1] += p * vv.y;
                o[i][2] += p * vv.z;
                o[i][3] += p * vv.w;
            }
        }
    }

#pragma unroll
    for (int i = 0; i < 4; i++) {
        float inv = 1.f / lr[i];
        float4 r;
        r.x = o[i][0] * inv; r.y = o[i][1] * inv;
        r.z = o[i][2] * inv; r.w = o[i][3] * inv;
        float* Og = O + ((size_t)(b * SS + q0 + tr * 4 + i) * NH + h) * HD + tc * 4;
        *(float4*)Og = r;
    }
}

// ---------------------------------------------------------------------------
extern "C" void kernel_launch(void* const* d_in, const int* in_sizes, int n_in,
                              void* d_out, int out_size) {
    (void)in_sizes; (void)n_in; (void)out_size;
    const float* x  = (const float*)d_in[0];
    const float* wq = (const float*)d_in[1];
    const float* bq = (const float*)d_in[2];
    const float* wk = (const float*)d_in[3];
    const float* bk = (const float*)d_in[4];
    const float* wv = (const float*)d_in[5];
    const float* bv = (const float*)d_in[6];
    const float* wo = (const float*)d_in[7];
    const float* bo = (const float*)d_in[8];
    float* out = (float*)d_out;

    float *qb, *kb, *vb, *ob;
    cudaGetSymbolAddress((void**)&qb, g_Q);
    cudaGetSymbolAddress((void**)&kb, g_K);
    cudaGetSymbolAddress((void**)&vb, g_V);
    cudaGetSymbolAddress((void**)&ob, g_O);
    __nv_bfloat16 *xs, *os, *wqs, *wks, *wvs, *wos;
    cudaGetSymbolAddress((void**)&xs,  g_xs);
    cudaGetSymbolAddress((void**)&os,  g_os);
    cudaGetSymbolAddress((void**)&wqs, g_wqs);
    cudaGetSymbolAddress((void**)&wks, g_wks);
    cudaGetSymbolAddress((void**)&wvs, g_wvs);
    cudaGetSymbolAddress((void**)&wos, g_wos);

    const int M = BB * SS;  // 4096
    const size_t fa_smem = 4 * 64 * FA_STRIDE * sizeof(float);
    cudaFuncSetAttribute(flash_attn, cudaFuncAttributeMaxDynamicSharedMemorySize,
                         (int)fa_smem);
    cudaFuncSetAttribute(gemm_mma, cudaFuncAttributeMaxDynamicSharedMemorySize,
                         GEMM_SMEM);

    // Split inputs/weights into bf16 hi/lo packed layouts
    split_hhl<<<(M * 2048 + 255) / 256, 256>>>(x, xs, M);
    split_hlh<<<(2048 * 2048 + 255) / 256, 256>>>(wq, wqs, 2048);
    split_hlh<<<(512 * 2048 + 255) / 256, 256>>>(wk, wks, 512);
    split_hlh<<<(512 * 2048 + 255) / 256, 256>>>(wv, wvs, 512);
    split_hlh<<<(2048 * 2048 + 255) / 256, 256>>>(wo, wos, 2048);

    // Projections on tensor cores (mma.sync bf16, 3-term split)
    dim3 gq(2048 / 128, M / 128);   // (16, 32)
    dim3 gkv(512 / 128, M / 128);   // (4, 32)
    gemm_mma<<<gq, 256, GEMM_SMEM>>>(xs, wqs, bq, qb, 2048);
    gemm_mma<<<gkv, 256, GEMM_SMEM>>>(xs, wks, bk, kb, 512);
    gemm_mma<<<gkv, 256, GEMM_SMEM>>>(xs, wvs, bv, vb, 512);

    // Attention (fp32)
    dim3 gf(SS / 64, NH, BB);
    flash_attn<<<gf, 256, fa_smem>>>(qb, kb, vb, ob);

    // Output projection
    split_hhl<<<(M * 2048 + 255) / 256, 256>>>(ob, os, M);
    gemm_mma<<<gq, 256, GEMM_SMEM>>>(os, wos, bo, out, 2048);
}

// round 5
// speedup vs baseline: 2.9780x; 2.0462x over previous
#include <cuda_runtime.h>
#include <cuda_bf16.h>
#include <math.h>
#include <stdint.h>

// Problem constants
#define BB 2
#define SS 2048
#define DD 2048
#define NH 32
#define NKV 8
#define HD 64
#define GG 4

#define GKP 6144          // split-K: 3 x 2048
#define NCHUNK 192        // 6144 / 32

// ---------------------------------------------------------------------------
// Scratch buffers
// ---------------------------------------------------------------------------
__device__ float g_Q[BB * SS * NH * HD];
__device__ float g_K[BB * SS * NKV * HD];
__device__ float g_V[BB * SS * NKV * HD];
__device__ float g_O[BB * SS * NH * HD];

__device__ __nv_bfloat16 g_xs[BB * SS * GKP];
__device__ __nv_bfloat16 g_os[BB * SS * GKP];
__device__ __nv_bfloat16 g_wqs[(NH * HD) * GKP];
__device__ __nv_bfloat16 g_wks[(NKV * HD) * GKP];
__device__ __nv_bfloat16 g_wvs[(NKV * HD) * GKP];
__device__ __nv_bfloat16 g_wos[DD * GKP];

__device__ __nv_bfloat16 g_Q3[BB * NH * SS * 192];    // [b][h][s][qh|ql|qh] (pre-scaled)
__device__ __nv_bfloat16 g_K3[BB * NKV * SS * 192];   // [b][kh][s][kh|kh|kl]
__device__ __nv_bfloat16 g_Vt[BB * NKV * 2 * HD * SS]; // [b][kh][plane][d][s]

// ---------------------------------------------------------------------------
__device__ __forceinline__ uint32_t smem_u32(const void* p) {
    uint32_t a;
    asm("{ .reg .u64 t; cvta.to.shared.u64 t, %1; cvt.u32.u64 %0, t; }"
        : "=r"(a) : "l"(p));
    return a;
}
__device__ __forceinline__ void cpa16(uint32_t s, const void* g) {
    asm volatile("cp.async.cg.shared.global [%0], [%1], 16;" :: "r"(s), "l"(g));
}
__device__ __forceinline__ void cpcommit() {
    asm volatile("cp.async.commit_group;");
}
__device__ __forceinline__ void cpwait0() {
    asm volatile("cp.async.wait_group 0;");
}
__device__ __forceinline__ void cpwait1() {
    asm volatile("cp.async.wait_group 1;");
}
__device__ __forceinline__ void ldsm4(uint32_t* r, uint32_t addr) {
    asm volatile("ldmatrix.sync.aligned.m8n8.x4.shared.b16 {%0,%1,%2,%3}, [%4];"
                 : "=r"(r[0]), "=r"(r[1]), "=r"(r[2]), "=r"(r[3]) : "r"(addr));
}
__device__ __forceinline__ void mma16816(float* d, const uint32_t* a, const uint32_t* b) {
    asm volatile(
        "mma.sync.aligned.m16n8k16.row.col.f32.bf16.bf16.f32 "
        "{%0,%1,%2,%3}, {%4,%5,%6,%7}, {%8,%9}, {%0,%1,%2,%3};"
        : "+f"(d[0]), "+f"(d[1]), "+f"(d[2]), "+f"(d[3])
        : "r"(a[0]), "r"(a[1]), "r"(a[2]), "r"(a[3]), "r"(b[0]), "r"(b[1]));
}

// ---------------------------------------------------------------------------
// Split kernels: fp32 [rows,2048] -> bf16 [rows,6144]
// ---------------------------------------------------------------------------
__global__ void split_hhl(const float* __restrict__ in,
                          __nv_bfloat16* __restrict__ out, int rows) {
    int idx = blockIdx.x * 256 + threadIdx.x;
    if (idx >= rows * 2048) return;
    int r = idx >> 11, c = idx & 2047;
    float v = in[idx];
    __nv_bfloat16 h = __float2bfloat16(v);
    __nv_bfloat16 l = __float2bfloat16(v - __bfloat162float(h));
    size_t o = (size_t)r * GKP + c;
    out[o] = h; out[o + 2048] = h; out[o + 4096] = l;
}

__global__ void split_hlh(const float* __restrict__ in,
                          __nv_bfloat16* __restrict__ out, int rows) {
    int idx = blockIdx.x * 256 + threadIdx.x;
    if (idx >= rows * 2048) return;
    int r = idx >> 11, c = idx & 2047;
    float v = in[idx];
    __nv_bfloat16 h = __float2bfloat16(v);
    __nv_bfloat16 l = __float2bfloat16(v - __bfloat162float(h));
    size_t o = (size_t)r * GKP + c;
    out[o] = h; out[o + 2048] = l; out[o + 4096] = h;
}

// ---------------------------------------------------------------------------
// Attention converters
// ---------------------------------------------------------------------------
__global__ void conv_q(const float* __restrict__ Q, __nv_bfloat16* __restrict__ out) {
    int idx = blockIdx.x * 256 + threadIdx.x;   // (b,s,h,d) order
    if (idx >= BB * SS * NH * HD) return;
    int d = idx & 63, h = (idx >> 6) & 31, s = (idx >> 11) & 2047, b = idx >> 22;
    float v = Q[idx] * 0.125f;                  // fold 1/sqrt(64)
    __nv_bfloat16 hi = __float2bfloat16(v);
    __nv_bfloat16 lo = __float2bfloat16(v - __bfloat162float(hi));
    size_t base = ((size_t)(b * NH + h) * SS + s) * 192 + d;
    out[base] = hi; out[base + 64] = lo; out[base + 128] = hi;
}

__global__ void conv_k(const float* __restrict__ K, __nv_bfloat16* __restrict__ out) {
    int idx = blockIdx.x * 256 + threadIdx.x;   // (b,s,kh,d)
    if (idx >= BB * SS * NKV * HD) return;
    int d = idx & 63, kh = (idx >> 6) & 7, s = (idx >> 9) & 2047, b = idx >> 20;
    float v = K[idx];
    __nv_bfloat16 hi = __float2bfloat16(v);
    __nv_bfloat16 lo = __float2bfloat16(v - __bfloat162float(hi));
    size_t base = ((size_t)(b * NKV + kh) * SS + s) * 192 + d;
    out[base] = hi; out[base + 64] = hi; out[base + 128] = lo;
}

__global__ void conv_v(const float* __restrict__ V, __nv_bfloat16* __restrict__ out) {
    int idx = blockIdx.x * 256 + threadIdx.x;   // (b,kh,d,s) output order
    if (idx >= BB * NKV * HD * SS) return;
    int s = idx & 2047, d = (idx >> 11) & 63, kh = (idx >> 17) & 7, b = idx >> 20;
    float v = V[((size_t)(b * SS + s) * NKV + kh) * HD + d];
    __nv_bfloat16 hi = __float2bfloat16(v);
    __nv_bfloat16 lo = __float2bfloat16(v - __bfloat162float(hi));
    size_t ph = (((size_t)(b * NKV + kh) * 2 + 0) * HD + d) * SS + s;
    size_t pl = (((size_t)(b * NKV + kh) * 2 + 1) * HD + d) * SS + s;
    out[ph] = hi; out[pl] = lo;
}

// ---------------------------------------------------------------------------
// bf16 warp-MMA GEMM: 128x128x32 tile, 4 warps (2x2), warp 64x64, 3 stages
// ---------------------------------------------------------------------------
#define SKW_B 80
#define A_TILE_B (128 * SKW_B)   // 10240
#define STAGE_B  (2 * A_TILE_B)  // 20480
#define GEMM_SMEM (3 * STAGE_B)  // 61440

__global__ __launch_bounds__(128, 2)
void gemm_mma(const __nv_bfloat16* __restrict__ A,
              const __nv_bfloat16* __restrict__ Bm,
              const float* __restrict__ bias,
              float* __restrict__ C, int N) {
    extern __shared__ __align__(128) char smem[];
    const uint32_t sb = smem_u32(smem);
    const int t = threadIdx.x;
    const int wid = t >> 5;
    const int lane = t & 31;
    const int wm = wid & 1;
    const int wn = wid >> 1;
    const int m0 = blockIdx.y * 128;
    const int n0 = blockIdx.x * 128;

    uint32_t soff[4];
    const __nv_bfloat16* ag[4];
    const __nv_bfloat16* bg[4];
#pragma unroll
    for (int i = 0; i < 4; i++) {
        int s = t + 128 * i;
        int r = s >> 2, sg = s & 3;
        soff[i] = (uint32_t)(r * SKW_B + sg * 16);
        ag[i] = A + (size_t)(m0 + r) * GKP + sg * 8;
        bg[i] = Bm + (size_t)(n0 + r) * GKP + sg * 8;
    }

    const int aRow = (lane & 7) + (lane & 8);
    const uint32_t aColB = (lane & 16) ? 16u : 0u;
    const int bRow = (lane & 7) + ((lane & 16) ? 8 : 0);
    const uint32_t bColB = (lane & 8) ? 16u : 0u;

    float acc[4][8][4];
#pragma unroll
    for (int i = 0; i < 4; i++)
#pragma unroll
        for (int j = 0; j < 8; j++)
#pragma unroll
            for (int r = 0; r < 4; r++) acc[i][j][r] = 0.f;

    // prologue: stages 0, 1
#pragma unroll
    for (int st = 0; st < 2; st++) {
        const uint32_t so = sb + st * STAGE_B;
        const int ko = st * 32;
#pragma unroll
        for (int i = 0; i < 4; i++) {
            cpa16(so + soff[i], ag[i] + ko);
            cpa16(so + A_TILE_B + soff[i], bg[i] + ko);
        }
        cpcommit();
    }

    for (int ch = 0; ch < NCHUNK; ch++) {
        if (ch + 1 < NCHUNK) cpwait1(); else cpwait0();
        __syncthreads();
        if (ch + 2 < NCHUNK) {
            const uint32_t so = sb + ((ch + 2) % 3) * STAGE_B;
            const int ko = (ch + 2) * 32;
#pragma unroll
            for (int i = 0; i < 4; i++) {
                cpa16(so + soff[i], ag[i] + ko);
                cpa16(so + A_TILE_B + soff[i], bg[i] + ko);
            }
            cpcommit();
        }

        const uint32_t Ab = sb + (ch % 3) * STAGE_B;
        const uint32_t Bb = Ab + A_TILE_B;
        const uint32_t aBase = Ab + (uint32_t)(wm * 64 + aRow) * SKW_B + aColB;
        const uint32_t bBase = Bb + (uint32_t)(wn * 64 + bRow) * SKW_B + bColB;

#pragma unroll
        for (int ks = 0; ks < 2; ks++) {
            uint32_t a[4][4];
            uint32_t b[8][2];
#pragma unroll
            for (int i = 0; i < 4; i++)
                ldsm4(a[i], aBase + (uint32_t)(i * 16) * SKW_B + ks * 32);
#pragma unroll
            for (int j2 = 0; j2 < 4; j2++) {
                uint32_t tmp[4];
                ldsm4(tmp, bBase + (uint32_t)(j2 * 16) * SKW_B + ks * 32);
                b[2 * j2][0] = tmp[0]; b[2 * j2][1] = tmp[1];
                b[2 * j2 + 1][0] = tmp[2]; b[2 * j2 + 1][1] = tmp[3];
            }
#pragma unroll
            for (int i = 0; i < 4; i++)
#pragma unroll
                for (int j = 0; j < 8; j++)
                    mma16816(acc[i][j], a[i], b[j]);
        }
        __syncthreads();
    }

#pragma unroll
    for (int i = 0; i < 4; i++) {
        const int r0 = m0 + wm * 64 + i * 16 + (lane >> 2);
#pragma unroll
        for (int j = 0; j < 8; j++) {
            const int c = n0 + wn * 64 + j * 8 + (lane & 3) * 2;
            const float b0 = bias[c], b1 = bias[c + 1];
            *(float2*)(C + (size_t)r0 * N + c) =
                make_float2(acc[i][j][0] + b0, acc[i][j][1] + b1);
            *(float2*)(C + (size_t)(r0 + 8) * N + c) =
                make_float2(acc[i][j][2] + b0, acc[i][j][3] + b1);
        }
    }
}

// ---------------------------------------------------------------------------
// Tensor-core flash attention.
// Q tile 128 rows, key tiles 64. 256 threads = 8 warps (4m x 2n).
// Scores: A=Q' [128][192], B=K' [64][192] (3-term split, scale pre-folded).
// PV: 3 passes (Ph*Vh, Pl*Vh, Ph*Vl), A=P [128][64], B=Vt [64d][64t].
// ---------------------------------------------------------------------------
#define AT_QS   0u
#define AT_ST0  51200u          // 128 rows * 400B
#define AT_STSZ 44032u          // K' 64*400 + Vt 2*64*144
#define AT_VOFF 25600u
#define AT_PH   183296u         // AT_ST0 + 3*AT_STSZ
#define AT_PL   (AT_PH + 18432u)
#define AT_RMAX (AT_PL + 18432u)
#define AT_RSUM (AT_RMAX + 1024u)
#define AT_SMEM 222208

__global__ __launch_bounds__(256, 1)
void attn_mma(const __nv_bfloat16* __restrict__ Q3,
              const __nv_bfloat16* __restrict__ K3,
              const __nv_bfloat16* __restrict__ Vt,
              float* __restrict__ O) {
    const int qtile = gridDim.x - 1 - blockIdx.x;   // longest first
    const int h = blockIdx.y;
    const int b = blockIdx.z;
    const int kh = h >> 2;
    const int q0 = qtile * 128;
    const int nkt = 2 * qtile + 2;

    extern __shared__ __align__(1024) char smem[];
    const uint32_t sb = smem_u32(smem);
    const int t = threadIdx.x;
    const int wid = t >> 5;
    const int lane = t & 31;
    const int wm = wid & 3;      // 4 m-warps (32 rows each)
    const int wn = wid >> 2;     // 2 n-warps (32 cols each)

    const int aRow = (lane & 7) + (lane & 8);
    const uint32_t aColB = (lane & 16) ? 16u : 0u;
    const int bRow = (lane & 7) + ((lane & 16) ? 8 : 0);
    const uint32_t bColB = (lane & 8) ? 16u : 0u;

    const __nv_bfloat16* Qg = Q3 + ((size_t)(b * NH + h) * SS + q0) * 192;
    const __nv_bfloat16* Kg = K3 + (size_t)(b * NKV + kh) * SS * 192;
    const __nv_bfloat16* Vg = Vt + (size_t)(b * NKV + kh) * 2 * HD * SS;

    // ---- prologue: Q tile + KV tiles 0,1 ----
    {
#pragma unroll
        for (int i = 0; i < 12; i++) {
            int sg = t + 256 * i;
            int r = sg / 24, c = sg % 24;
            cpa16(sb + AT_QS + r * 400 + c * 16, Qg + (size_t)r * 192 + c * 8);
        }
        // KV tile 0 into stage 0 (same commit group as Q)
        {
            const uint32_t so = sb + AT_ST0;
#pragma unroll
            for (int i = 0; i < 6; i++) {
                int sg = t + 256 * i;
                int r = sg / 24, c = sg % 24;
                cpa16(so + r * 400 + c * 16, Kg + (size_t)r * 192 + c * 8);
            }
#pragma unroll
            for (int i = 0; i < 4; i++) {
                int sg = t + 256 * i;
                int p = sg >> 9, d = (sg >> 3) & 63, c = sg & 7;
                cpa16(so + AT_VOFF + p * 9216 + d * 144 + c * 16,
                      Vg + ((size_t)(p * HD + d)) * SS + c * 8);
            }
        }
        cpcommit();
        // KV tile 1 into stage 1
        {
            const uint32_t so = sb + AT_ST0 + AT_STSZ;
#pragma unroll
            for (int i = 0; i < 6; i++) {
                int sg = t + 256 * i;
                int r = sg / 24, c = sg % 24;
                cpa16(so + r * 400 + c * 16, Kg + (size_t)(64 + r) * 192 + c * 8);
            }
#pragma unroll
            for (int i = 0; i < 4; i++) {
                int sg = t + 256 * i;
                int p = sg >> 9, d = (sg >> 3) & 63, c = sg & 7;
                cpa16(so + AT_VOFF + p * 9216 + d * 144 + c * 16,
                      Vg + ((size_t)(p * HD + d)) * SS + 64 + c * 8);
            }
        }
        cpcommit();
    }

    float acc_o[2][4][4];
    float m_st[2][2], l_st[2][2];
#pragma unroll
    for (int mi = 0; mi < 2; mi++) {
#pragma unroll
        for (int j = 0; j < 4; j++)
#pragma unroll
            for (int r = 0; r < 4; r++) acc_o[mi][j][r] = 0.f;
        m_st[mi][0] = m_st[mi][1] = -1e30f;
        l_st[mi][0] = l_st[mi][1] = 0.f;
    }

    for (int kt = 0; kt < nkt; kt++) {
        if (kt + 1 < nkt) cpwait1(); else cpwait0();
        __syncthreads();

        // prefetch kt+2 into stage (kt+2)%3
        if (kt + 2 < nkt) {
            const uint32_t so = sb + AT_ST0 + ((kt + 2) % 3) * AT_STSZ;
            const int k0 = (kt + 2) * 64;
#pragma unroll
            for (int i = 0; i < 6; i++) {
                int sg = t + 256 * i;
                int r = sg / 24, c = sg % 24;
                cpa16(so + r * 400 + c * 16, Kg + (size_t)(k0 + r) * 192 + c * 8);
            }
#pragma unroll
            for (int i = 0; i < 4; i++) {
                int sg = t + 256 * i;
                int p = sg >> 9, d = (sg >> 3) & 63, c = sg & 7;
                cpa16(so + AT_VOFF + p * 9216 + d * 144 + c * 16,
                      Vg + ((size_t)(p * HD + d)) * SS + k0 + c * 8);
            }
            cpcommit();
        }

        const uint32_t stOff = sb + AT_ST0 + (kt % 3) * AT_STSZ;

        // ---- scores: S = Q' . K'^T (3-term split over 192) ----
        float s[2][4][4];
#pragma unroll
        for (int mi = 0; mi < 2; mi++)
#pragma unroll
            for (int j = 0; j < 4; j++)
#pragma unroll
                for (int r = 0; r < 4; r++) s[mi][j][r] = 0.f;

        const uint32_t aQ = sb + AT_QS + (uint32_t)(wm * 32 + aRow) * 400 + aColB;
        const uint32_t bK = stOff + (uint32_t)(wn * 32 + bRow) * 400 + bColB;
#pragma unroll
        for (int ks = 0; ks < 12; ks++) {
            uint32_t a[2][4], bb[4][2];
#pragma unroll
            for (int mi = 0; mi < 2; mi++)
                ldsm4(a[mi], aQ + (uint32_t)(mi * 16) * 400 + ks * 32);
#pragma unroll
            for (int j2 = 0; j2 < 2; j2++) {
                uint32_t tmp[4];
                ldsm4(tmp, bK + (uint32_t)(j2 * 16) * 400 + ks * 32);
                bb[2 * j2][0] = tmp[0]; bb[2 * j2][1] = tmp[1];
                bb[2 * j2 + 1][0] = tmp[2]; bb[2 * j2 + 1][1] = tmp[3];
            }
#pragma unroll
            for (int mi = 0; mi < 2; mi++)
#pragma unroll
                for (int j = 0; j < 4; j++)
                    mma16816(s[mi][j], a[mi], bb[j]);
        }

        // ---- causal mask (only diagonal tiles) ----
        if (kt >= 2 * qtile) {
#pragma unroll
            for (int mi = 0; mi < 2; mi++)
#pragma unroll
                for (int j = 0; j < 4; j++)
#pragma unroll
                    for (int r = 0; r < 4; r++) {
                        int col = kt * 64 + wn * 32 + j * 8 + (lane & 3) * 2 + (r & 1);
                        int row = q0 + wm * 32 + mi * 16 + (lane >> 2) + (r >> 1) * 8;
                        if (col > row) s[mi][j][r] = -1e30f;
                    }
        }

        // ---- row max ----
        float* redmax = (float*)(smem + AT_RMAX);
        float* redsum = (float*)(smem + AT_RSUM);
#pragma unroll
        for (int mi = 0; mi < 2; mi++)
#pragma unroll
            for (int ri = 0; ri < 2; ri++) {
                float mx = -1e30f;
#pragma unroll
                for (int j = 0; j < 4; j++)
                    mx = fmaxf(mx, fmaxf(s[mi][j][ri * 2], s[mi][j][ri * 2 + 1]));
                mx = fmaxf(mx, __shfl_xor_sync(0xffffffffu, mx, 1));
                mx = fmaxf(mx, __shfl_xor_sync(0xffffffffu, mx, 2));
                if ((lane & 3) == 0) {
                    int row = wm * 32 + mi * 16 + (lane >> 2) + ri * 8;
                    redmax[row * 2 + wn] = mx;
                }
            }
        __syncthreads();

        float alpha[2][2], mnow[2][2];
#pragma unroll
        for (int mi = 0; mi < 2; mi++)
#pragma unroll
            for (int ri = 0; ri < 2; ri++) {
                int row = wm * 32 + mi * 16 + (lane >> 2) + ri * 8;
                float tm = fmaxf(redmax[row * 2], redmax[row * 2 + 1]);
                float mn = fmaxf(m_st[mi][ri], tm);
                alpha[mi][ri] = __expf(m_st[mi][ri] - mn);
                m_st[mi][ri] = mn;
                mnow[mi][ri] = mn;
            }
        // rescale O
#pragma unroll
        for (int mi = 0; mi < 2; mi++)
#pragma unroll
            for (int j = 0; j < 4; j++)
#pragma unroll
                for (int r = 0; r < 4; r++) acc_o[mi][j][r] *= alpha[mi][r >> 1];

        // ---- exp, P hi/lo store, row sums ----
#pragma unroll
        for (int mi = 0; mi < 2; mi++)
#pragma unroll
            for (int ri = 0; ri < 2; ri++) {
                float sum = 0.f;
                const int row = wm * 32 + mi * 16 + (lane >> 2) + ri * 8;
                const float mrow = mnow[mi][ri];
#pragma unroll
                for (int j = 0; j < 4; j++) {
                    float p0 = __expf(s[mi][j][ri * 2] - mrow);
                    float p1 = __expf(s[mi][j][ri * 2 + 1] - mrow);
                    sum += p0 + p1;
                    __nv_bfloat16 h0 = __float2bfloat16(p0);
                    __nv_bfloat16 h1 = __float2bfloat16(p1);
                    __nv_bfloat16 l0 = __float2bfloat16(p0 - __bfloat162float(h0));
                    __nv_bfloat16 l1 = __float2bfloat16(p1 - __bfloat162float(h1));
                    uint32_t off = (uint32_t)row * 144 +
                                   (uint32_t)(wn * 32 + j * 8 + (lane & 3) * 2) * 2;
                    __nv_bfloat162 hv; hv.x = h0; hv.y = h1;
                    __nv_bfloat162 lv; lv.x = l0; lv.y = l1;
                    *(__nv_bfloat162*)(smem + AT_PH + off) = hv;
                    *(__nv_bfloat162*)(smem + AT_PL + off) = lv;
                }
                sum += __shfl_xor_sync(0xffffffffu, sum, 1);
                sum += __shfl_xor_sync(0xffffffffu, sum, 2);
                if ((lane & 3) == 0) redsum[row * 2 + wn] = sum;
            }
        __syncthreads();

#pragma unroll
        for (int mi = 0; mi < 2; mi++)
#pragma unroll
            for (int ri = 0; ri < 2; ri++) {
                int row = wm * 32 + mi * 16 + (lane >> 2) + ri * 8;
                l_st[mi][ri] = l_st[mi][ri] * alpha[mi][ri] +
                               redsum[row * 2] + redsum[row * 2 + 1];
            }

        // ---- PV: 3 passes ----
#pragma unroll
        for (int pass = 0; pass < 3; pass++) {
            const uint32_t Aoff = (pass == 1) ? AT_PL : AT_PH;
            const uint32_t plane = (pass == 2) ? 1u : 0u;
            const uint32_t aP = sb + Aoff + (uint32_t)(wm * 32 + aRow) * 144 + aColB;
            const uint32_t bV = stOff + AT_VOFF + plane * 9216 +
                                (uint32_t)(wn * 32 + bRow) * 144 + bColB;
#pragma unroll
            for (int ks = 0; ks < 4; ks++) {
                uint32_t a[2][4], bb[4][2];
#pragma unroll
                for (int mi = 0; mi < 2; mi++)
                    ldsm4(a[mi], aP + (uint32_t)(mi * 16) * 144 + ks * 32);
#pragma unroll
                for (int j2 = 0; j2 < 2; j2++) {
                    uint32_t tmp[4];
                    ldsm4(tmp, bV + (uint32_t)(j2 * 16) * 144 + ks * 32);
                    bb[2 * j2][0] = tmp[0]; bb[2 * j2][1] = tmp[1];
                    bb[2 * j2 + 1][0] = tmp[2]; bb[2 * j2 + 1][1] = tmp[3];
                }
#pragma unroll
                for (int mi = 0; mi < 2; mi++)
#pragma unroll
                    for (int j = 0; j < 4; j++)
                        mma16816(acc_o[mi][j], a[mi], bb[j]);
            }
        }
    }

    // ---- epilogue ----
#pragma unroll
    for (int mi = 0; mi < 2; mi++)
#pragma unroll
        for (int ri = 0; ri < 2; ri++) {
            const float inv = 1.f / l_st[mi][ri];
            const int srow = q0 + wm * 32 + mi * 16 + (lane >> 2) + ri * 8;
#pragma unroll
            for (int j = 0; j < 4; j++) {
                const int d0 = wn * 32 + j * 8 + (lane & 3) * 2;
                float2 v = make_float2(acc_o[mi][j][ri * 2] * inv,
                                       acc_o[mi][j][ri * 2 + 1] * inv);
                *(float2*)(O + ((size_t)(b * SS + srow) * NH + h) * HD + d0) = v;
            }
        }
}

// ---------------------------------------------------------------------------
extern "C" void kernel_launch(void* const* d_in, const int* in_sizes, int n_in,
                              void* d_out, int out_size) {
    (void)in_sizes; (void)n_in; (void)out_size;
    const float* x  = (const float*)d_in[0];
    const float* wq = (const float*)d_in[1];
    const float* bq = (const float*)d_in[2];
    const float* wk = (const float*)d_in[3];
    const float* bk = (const float*)d_in[4];
    const float* wv = (const float*)d_in[5];
    const float* bv = (const float*)d_in[6];
    const float* wo = (const float*)d_in[7];
    const float* bo = (const float*)d_in[8];
    float* out = (float*)d_out;

    float *qb, *kb, *vb, *ob;
    cudaGetSymbolAddress((void**)&qb, g_Q);
    cudaGetSymbolAddress((void**)&kb, g_K);
    cudaGetSymbolAddress((void**)&vb, g_V);
    cudaGetSymbolAddress((void**)&ob, g_O);
    __nv_bfloat16 *xs, *os, *wqs, *wks, *wvs, *wos, *q3, *k3, *vt;
    cudaGetSymbolAddress((void**)&xs,  g_xs);
    cudaGetSymbolAddress((void**)&os,  g_os);
    cudaGetSymbolAddress((void**)&wqs, g_wqs);
    cudaGetSymbolAddress((void**)&wks, g_wks);
    cudaGetSymbolAddress((void**)&wvs, g_wvs);
    cudaGetSymbolAddress((void**)&wos, g_wos);
    cudaGetSymbolAddress((void**)&q3,  g_Q3);
    cudaGetSymbolAddress((void**)&k3,  g_K3);
    cudaGetSymbolAddress((void**)&vt,  g_Vt);

    const int M = BB * SS;  // 4096
    cudaFuncSetAttribute(gemm_mma, cudaFuncAttributeMaxDynamicSharedMemorySize,
                         GEMM_SMEM);
    cudaFuncSetAttribute(attn_mma, cudaFuncAttributeMaxDynamicSharedMemorySize,
                         AT_SMEM);

    // Split inputs/weights into bf16 hi/lo packed layouts
    split_hhl<<<(M * 2048 + 255) / 256, 256>>>(x, xs, M);
    split_hlh<<<(2048 * 2048 + 255) / 256, 256>>>(wq, wqs, 2048);
    split_hlh<<<(512 * 2048 + 255) / 256, 256>>>(wk, wks, 512);
    split_hlh<<<(512 * 2048 + 255) / 256, 256>>>(wv, wvs, 512);
    split_hlh<<<(2048 * 2048 + 255) / 256, 256>>>(wo, wos, 2048);

    // Projections
    dim3 gq(2048 / 128, M / 128);
    dim3 gkv(512 / 128, M / 128);
    gemm_mma<<<gq, 128, GEMM_SMEM>>>(xs, wqs, bq, qb, 2048);
    gemm_mma<<<gkv, 128, GEMM_SMEM>>>(xs, wks, bk, kb, 512);
    gemm_mma<<<gkv, 128, GEMM_SMEM>>>(xs, wvs, bv, vb, 512);

    // Convert Q/K/V for tensor-core attention
    conv_q<<<(BB * SS * NH * HD + 255) / 256, 256>>>(qb, q3);
    conv_k<<<(BB * SS * NKV * HD + 255) / 256, 256>>>(kb, k3);
    conv_v<<<(BB * NKV * HD * SS + 255) / 256, 256>>>(vb, vt);

    // Attention (tensor cores)
    dim3 ga(SS / 128, NH, BB);
    attn_mma<<<ga, 256, AT_SMEM>>>(q3, k3, vt, ob);

    // Output projection
    split_hhl<<<(M * 2048 + 255) / 256, 256>>>(ob, os, M);
    gemm_mma<<<gq, 128, GEMM_SMEM>>>(os, wos, bo, out, 2048);
}

// round 6
// speedup vs baseline: 3.2811x; 1.1018x over previous
#include <cuda_runtime.h>
#include <cuda_bf16.h>
#include <math.h>
#include <stdint.h>

// Problem constants
#define BB 2
#define SS 2048
#define DD 2048
#define NH 32
#define NKV 8
#define HD 64
#define GG 4

#define GKP 6144          // split-K: 3 x 2048
#define NCHUNK 192        // 6144 / 32

// ---------------------------------------------------------------------------
// Scratch buffers
// ---------------------------------------------------------------------------
__device__ __nv_bfloat16 g_xs[BB * SS * GKP];          // x split (hi,hi,lo)
__device__ __nv_bfloat16 g_os[BB * SS * GKP];          // attn out split (hi,hi,lo)
__device__ __nv_bfloat16 g_wqkvs[3072 * GKP];          // [wq;wk;wv] split (hi,lo,hi)
__device__ __nv_bfloat16 g_wos[DD * GKP];

__device__ __nv_bfloat16 g_Q3[BB * NH * SS * 192];     // [b][h][s][qh|ql|qh] (scaled)
__device__ __nv_bfloat16 g_K3[BB * NKV * SS * 192];    // [b][kh][s][kh|kh|kl]
__device__ __nv_bfloat16 g_Vt[BB * NKV * 2 * HD * SS]; // [b][kh][plane][d][s]

// ---------------------------------------------------------------------------
__device__ __forceinline__ uint32_t smem_u32(const void* p) {
    uint32_t a;
    asm("{ .reg .u64 t; cvta.to.shared.u64 t, %1; cvt.u32.u64 %0, t; }"
        : "=r"(a) : "l"(p));
    return a;
}
__device__ __forceinline__ void cpa16(uint32_t s, const void* g) {
    asm volatile("cp.async.cg.shared.global [%0], [%1], 16;" :: "r"(s), "l"(g));
}
__device__ __forceinline__ void cpcommit() { asm volatile("cp.async.commit_group;"); }
__device__ __forceinline__ void cpwait0() { asm volatile("cp.async.wait_group 0;"); }
__device__ __forceinline__ void cpwait1() { asm volatile("cp.async.wait_group 1;"); }
__device__ __forceinline__ void cpwait2() { asm volatile("cp.async.wait_group 2;"); }
__device__ __forceinline__ void ldsm4(uint32_t* r, uint32_t addr) {
    asm volatile("ldmatrix.sync.aligned.m8n8.x4.shared.b16 {%0,%1,%2,%3}, [%4];"
                 : "=r"(r[0]), "=r"(r[1]), "=r"(r[2]), "=r"(r[3]) : "r"(addr));
}
__device__ __forceinline__ void mma16816(float* d, const uint32_t* a, const uint32_t* b) {
    asm volatile(
        "mma.sync.aligned.m16n8k16.row.col.f32.bf16.bf16.f32 "
        "{%0,%1,%2,%3}, {%4,%5,%6,%7}, {%8,%9}, {%0,%1,%2,%3};"
        : "+f"(d[0]), "+f"(d[1]), "+f"(d[2]), "+f"(d[3])
        : "r"(a[0]), "r"(a[1]), "r"(a[2]), "r"(a[3]), "r"(b[0]), "r"(b[1]));
}
__device__ __forceinline__ void split2(float v0, float v1,
                                       __nv_bfloat162& hi, __nv_bfloat162& lo) {
    __nv_bfloat16 h0 = __float2bfloat16(v0), h1 = __float2bfloat16(v1);
    hi.x = h0; hi.y = h1;
    lo.x = __float2bfloat16(v0 - __bfloat162float(h0));
    lo.y = __float2bfloat16(v1 - __bfloat162float(h1));
}

// ---------------------------------------------------------------------------
// Split kernels: fp32 [rows,2048] -> bf16 [rows,6144]
// ---------------------------------------------------------------------------
__global__ void split_hhl(const float* __restrict__ in,
                          __nv_bfloat16* __restrict__ out, int rows) {
    int idx = blockIdx.x * 256 + threadIdx.x;
    if (idx >= rows * 2048) return;
    int r = idx >> 11, c = idx & 2047;
    float v = in[idx];
    __nv_bfloat16 h = __float2bfloat16(v);
    __nv_bfloat16 l = __float2bfloat16(v - __bfloat162float(h));
    size_t o = (size_t)r * GKP + c;
    out[o] = h; out[o + 2048] = h; out[o + 4096] = l;
}

__global__ void split_hlh(const float* __restrict__ in,
                          __nv_bfloat16* __restrict__ out, int rows) {
    int idx = blockIdx.x * 256 + threadIdx.x;
    if (idx >= rows * 2048) return;
    int r = idx >> 11, c = idx & 2047;
    float v = in[idx];
    __nv_bfloat16 h = __float2bfloat16(v);
    __nv_bfloat16 l = __float2bfloat16(v - __bfloat162float(h));
    size_t o = (size_t)r * GKP + c;
    out[o] = h; out[o + 2048] = l; out[o + 4096] = h;
}

// ---------------------------------------------------------------------------
// GEMM mainloop macros (128x128x32 tile, 4 warps 2x2, warp 64x64, 4 stages)
// ---------------------------------------------------------------------------
#define SKW_B 80
#define A_TILE_B (128 * SKW_B)   // 10240
#define STAGE_B  (2 * A_TILE_B)  // 20480
#define GEMM_SMEM (4 * STAGE_B)  // 81920

#define GEMM_PROLOG(Abuf, Bbuf)                                               \
    extern __shared__ __align__(128) char smem[];                             \
    const uint32_t sb = smem_u32(smem);                                       \
    const int t = threadIdx.x;                                                \
    const int wid = t >> 5;                                                   \
    const int lane = t & 31;                                                  \
    const int wm = wid & 1;                                                   \
    const int wn = wid >> 1;                                                  \
    const int m0 = blockIdx.y * 128;                                          \
    const int n0 = blockIdx.x * 128;                                          \
    uint32_t soff[4];                                                         \
    const __nv_bfloat16* ag[4];                                               \
    const __nv_bfloat16* bg[4];                                               \
    _Pragma("unroll")                                                         \
    for (int i = 0; i < 4; i++) {                                             \
        int s = t + 128 * i;                                                  \
        int r = s >> 2, sg = s & 3;                                           \
        soff[i] = (uint32_t)(r * SKW_B + sg * 16);                            \
        ag[i] = (Abuf) + (size_t)(m0 + r) * GKP + sg * 8;                     \
        bg[i] = (Bbuf) + (size_t)(n0 + r) * GKP + sg * 8;                     \
    }                                                                         \
    const int aRow = (lane & 7) + (lane & 8);                                 \
    const uint32_t aColB = (lane & 16) ? 16u : 0u;                            \
    const int bRow = (lane & 7) + ((lane & 16) ? 8 : 0);                      \
    const uint32_t bColB = (lane & 8) ? 16u : 0u;                             \
    float acc[4][8][4];                                                       \
    _Pragma("unroll")                                                         \
    for (int i = 0; i < 4; i++)                                               \
        _Pragma("unroll")                                                     \
        for (int j = 0; j < 8; j++)                                           \
            _Pragma("unroll")                                                 \
            for (int r = 0; r < 4; r++) acc[i][j][r] = 0.f;                   \
    _Pragma("unroll")                                                         \
    for (int st = 0; st < 3; st++) {                                          \
        const uint32_t so = sb + st * STAGE_B;                                \
        const int ko = st * 32;                                               \
        _Pragma("unroll")                                                     \
        for (int i = 0; i < 4; i++) {                                         \
            cpa16(so + soff[i], ag[i] + ko);                                  \
            cpa16(so + A_TILE_B + soff[i], bg[i] + ko);                       \
        }                                                                     \
        cpcommit();                                                           \
    }                                                                         \
    for (int ch = 0; ch < NCHUNK; ch++) {                                     \
        const int rem = NCHUNK - 1 - ch;                                      \
        if (rem >= 2) cpwait2(); else if (rem == 1) cpwait1(); else cpwait0();\
        __syncthreads();                                                      \
        if (ch + 3 < NCHUNK) {                                                \
            const uint32_t so = sb + ((ch + 3) & 3) * STAGE_B;                \
            const int ko = (ch + 3) * 32;                                     \
            _Pragma("unroll")                                                 \
            for (int i = 0; i < 4; i++) {                                     \
                cpa16(so + soff[i], ag[i] + ko);                              \
                cpa16(so + A_TILE_B + soff[i], bg[i] + ko);                   \
            }                                                                 \
            cpcommit();                                                       \
        }                                                                     \
        const uint32_t Ab = sb + (ch & 3) * STAGE_B;                          \
        const uint32_t Bb = Ab + A_TILE_B;                                    \
        const uint32_t aBase = Ab + (uint32_t)(wm * 64 + aRow) * SKW_B + aColB;\
        const uint32_t bBase = Bb + (uint32_t)(wn * 64 + bRow) * SKW_B + bColB;\
        _Pragma("unroll")                                                     \
        for (int ks = 0; ks < 2; ks++) {                                      \
            uint32_t a[4][4];                                                 \
            uint32_t b[8][2];                                                 \
            _Pragma("unroll")                                                 \
            for (int i = 0; i < 4; i++)                                       \
                ldsm4(a[i], aBase + (uint32_t)(i * 16) * SKW_B + ks * 32);    \
            _Pragma("unroll")                                                 \
            for (int j2 = 0; j2 < 4; j2++) {                                  \
                uint32_t tmp[4];                                              \
                ldsm4(tmp, bBase + (uint32_t)(j2 * 16) * SKW_B + ks * 32);    \
                b[2 * j2][0] = tmp[0]; b[2 * j2][1] = tmp[1];                 \
                b[2 * j2 + 1][0] = tmp[2]; b[2 * j2 + 1][1] = tmp[3];         \
            }                                                                 \
            _Pragma("unroll")                                                 \
            for (int i = 0; i < 4; i++)                                       \
                _Pragma("unroll")                                             \
                for (int j = 0; j < 8; j++)                                   \
                    mma16816(acc[i][j], a[i], b[j]);                          \
        }                                                                     \
    }

// ---------------------------------------------------------------------------
// O-projection GEMM: fp32 C = A.B^T + bias
// ---------------------------------------------------------------------------
__global__ __launch_bounds__(128, 2)
void gemm_mma(const __nv_bfloat16* __restrict__ A,
              const __nv_bfloat16* __restrict__ Bm,
              const float* __restrict__ bias,
              float* __restrict__ C, int N) {
    GEMM_PROLOG(A, Bm)

#pragma unroll
    for (int i = 0; i < 4; i++) {
        const int r0 = m0 + wm * 64 + i * 16 + (lane >> 2);
#pragma unroll
        for (int j = 0; j < 8; j++) {
            const int c = n0 + wn * 64 + j * 8 + (lane & 3) * 2;
            const float b0 = bias[c], b1 = bias[c + 1];
            *(float2*)(C + (size_t)r0 * N + c) =
                make_float2(acc[i][j][0] + b0, acc[i][j][1] + b1);
            *(float2*)(C + (size_t)(r0 + 8) * N + c) =
                make_float2(acc[i][j][2] + b0, acc[i][j][3] + b1);
        }
    }
}

// ---------------------------------------------------------------------------
// Fused QKV GEMM: writes directly into attention formats.
//   n < 2048           : Q -> g_Q3 (scaled by 0.125, hi|lo|hi)
//   2048 <= n < 2560   : K -> g_K3 (hi|hi|lo)
//   n >= 2560          : V -> g_Vt (transposed [d][s], hi/lo planes)
// ---------------------------------------------------------------------------
__global__ __launch_bounds__(128, 2)
void gemm_qkv(const __nv_bfloat16* __restrict__ A,
              const __nv_bfloat16* __restrict__ Bm,
              const float* __restrict__ bq,
              const float* __restrict__ bk,
              const float* __restrict__ bv,
              __nv_bfloat16* __restrict__ Q3,
              __nv_bfloat16* __restrict__ K3,
              __nv_bfloat16* __restrict__ Vt) {
    GEMM_PROLOG(A, Bm)

    const int mode = (blockIdx.x < 16) ? 0 : (blockIdx.x < 20 ? 1 : 2);
    const float* bias = (mode == 0) ? bq : (mode == 1 ? bk : bv);
    const int creg0 = (mode == 0) ? 0 : (mode == 1 ? 2048 : 2560);

#pragma unroll
    for (int i = 0; i < 4; i++) {
#pragma unroll
        for (int rr = 0; rr < 2; rr++) {
            const int row = m0 + wm * 64 + i * 16 + (lane >> 2) + rr * 8;
            const int b = row >> 11, s = row & 2047;
#pragma unroll
            for (int j = 0; j < 8; j++) {
                const int cb = n0 + wn * 64 + j * 8 + (lane & 3) * 2 - creg0;
                const int hh = cb >> 6;       // head (or kv-head)
                const int d = cb & 63;
                float v0 = acc[i][j][rr * 2 + 0] + bias[cb];
                float v1 = acc[i][j][rr * 2 + 1] + bias[cb + 1];
                if (mode == 0) { v0 *= 0.125f; v1 *= 0.125f; }
                __nv_bfloat162 hi, lo;
                split2(v0, v1, hi, lo);
                if (mode == 0) {
                    __nv_bfloat16* base =
                        Q3 + ((size_t)(b * NH + hh) * SS + s) * 192 + d;
                    *(__nv_bfloat162*)(base) = hi;
                    *(__nv_bfloat162*)(base + 64) = lo;
                    *(__nv_bfloat162*)(base + 128) = hi;
                } else if (mode == 1) {
                    __nv_bfloat16* base =
                        K3 + ((size_t)(b * NKV + hh) * SS + s) * 192 + d;
                    *(__nv_bfloat162*)(base) = hi;
                    *(__nv_bfloat162*)(base + 64) = hi;
                    *(__nv_bfloat162*)(base + 128) = lo;
                } else {
                    __nv_bfloat16* base =
                        Vt + (((size_t)(b * NKV + hh) * 2) * HD + d) * SS + s;
                    base[0] = hi.x;
                    base[SS] = hi.y;
                    base[HD * SS] = lo.x;
                    base[HD * SS + SS] = lo.y;
                }
            }
        }
    }
}

// ---------------------------------------------------------------------------
// Tensor-core flash attention (output fused to split-hhl bf16 g_os).
// ---------------------------------------------------------------------------
#define AT_QS   0u
#define AT_ST0  51200u
#define AT_STSZ 44032u
#define AT_VOFF 25600u
#define AT_PH   183296u
#define AT_PL   (AT_PH + 18432u)
#define AT_RMAX (AT_PL + 18432u)
#define AT_RSUM (AT_RMAX + 1024u)
#define AT_SMEM 222208

__global__ __launch_bounds__(256, 1)
void attn_mma(const __nv_bfloat16* __restrict__ Q3,
              const __nv_bfloat16* __restrict__ K3,
              const __nv_bfloat16* __restrict__ Vt,
              __nv_bfloat16* __restrict__ Os) {
    const int qtile = gridDim.x - 1 - blockIdx.x;
    const int h = blockIdx.y;
    const int b = blockIdx.z;
    const int kh = h >> 2;
    const int q0 = qtile * 128;
    const int nkt = 2 * qtile + 2;

    extern __shared__ __align__(1024) char smem[];
    const uint32_t sb = smem_u32(smem);
    const int t = threadIdx.x;
    const int wid = t >> 5;
    const int lane = t & 31;
    const int wm = wid & 3;
    const int wn = wid >> 2;

    const int aRow = (lane & 7) + (lane & 8);
    const uint32_t aColB = (lane & 16) ? 16u : 0u;
    const int bRow = (lane & 7) + ((lane & 16) ? 8 : 0);
    const uint32_t bColB = (lane & 8) ? 16u : 0u;

    const __nv_bfloat16* Qg = Q3 + ((size_t)(b * NH + h) * SS + q0) * 192;
    const __nv_bfloat16* Kg = K3 + (size_t)(b * NKV + kh) * SS * 192;
    const __nv_bfloat16* Vg = Vt + (size_t)(b * NKV + kh) * 2 * HD * SS;

    {
#pragma unroll
        for (int i = 0; i < 12; i++) {
            int sg = t + 256 * i;
            int r = sg / 24, c = sg % 24;
            cpa16(sb + AT_QS + r * 400 + c * 16, Qg + (size_t)r * 192 + c * 8);
        }
        {
            const uint32_t so = sb + AT_ST0;
#pragma unroll
            for (int i = 0; i < 6; i++) {
                int sg = t + 256 * i;
                int r = sg / 24, c = sg % 24;
                cpa16(so + r * 400 + c * 16, Kg + (size_t)r * 192 + c * 8);
            }
#pragma unroll
            for (int i = 0; i < 4; i++) {
                int sg = t + 256 * i;
                int p = sg >> 9, d = (sg >> 3) & 63, c = sg & 7;
                cpa16(so + AT_VOFF + p * 9216 + d * 144 + c * 16,
                      Vg + ((size_t)(p * HD + d)) * SS + c * 8);
            }
        }
        cpcommit();
        {
            const uint32_t so = sb + AT_ST0 + AT_STSZ;
#pragma unroll
            for (int i = 0; i < 6; i++) {
                int sg = t + 256 * i;
                int r = sg / 24, c = sg % 24;
                cpa16(so + r * 400 + c * 16, Kg + (size_t)(64 + r) * 192 + c * 8);
            }
#pragma unroll
            for (int i = 0; i < 4; i++) {
                int sg = t + 256 * i;
                int p = sg >> 9, d = (sg >> 3) & 63, c = sg & 7;
                cpa16(so + AT_VOFF + p * 9216 + d * 144 + c * 16,
                      Vg + ((size_t)(p * HD + d)) * SS + 64 + c * 8);
            }
        }
        cpcommit();
    }

    float acc_o[2][4][4];
    float m_st[2][2], l_st[2][2];
#pragma unroll
    for (int mi = 0; mi < 2; mi++) {
#pragma unroll
        for (int j = 0; j < 4; j++)
#pragma unroll
            for (int r = 0; r < 4; r++) acc_o[mi][j][r] = 0.f;
        m_st[mi][0] = m_st[mi][1] = -1e30f;
        l_st[mi][0] = l_st[mi][1] = 0.f;
    }

    for (int kt = 0; kt < nkt; kt++) {
        if (kt + 1 < nkt) cpwait1(); else cpwait0();
        __syncthreads();

        if (kt + 2 < nkt) {
            const uint32_t so = sb + AT_ST0 + ((kt + 2) % 3) * AT_STSZ;
            const int k0 = (kt + 2) * 64;
#pragma unroll
            for (int i = 0; i < 6; i++) {
                int sg = t + 256 * i;
                int r = sg / 24, c = sg % 24;
                cpa16(so + r * 400 + c * 16, Kg + (size_t)(k0 + r) * 192 + c * 8);
            }
#pragma unroll
            for (int i = 0; i < 4; i++) {
                int sg = t + 256 * i;
                int p = sg >> 9, d = (sg >> 3) & 63, c = sg & 7;
                cpa16(so + AT_VOFF + p * 9216 + d * 144 + c * 16,
                      Vg + ((size_t)(p * HD + d)) * SS + k0 + c * 8);
            }
            cpcommit();
        }

        const uint32_t stOff = sb + AT_ST0 + (kt % 3) * AT_STSZ;

        float s[2][4][4];
#pragma unroll
        for (int mi = 0; mi < 2; mi++)
#pragma unroll
            for (int j = 0; j < 4; j++)
#pragma unroll
                for (int r = 0; r < 4; r++) s[mi][j][r] = 0.f;

        const uint32_t aQ = sb + AT_QS + (uint32_t)(wm * 32 + aRow) * 400 + aColB;
        const uint32_t bK = stOff + (uint32_t)(wn * 32 + bRow) * 400 + bColB;
#pragma unroll
        for (int ks = 0; ks < 12; ks++) {
            uint32_t a[2][4], bb[4][2];
#pragma unroll
            for (int mi = 0; mi < 2; mi++)
                ldsm4(a[mi], aQ + (uint32_t)(mi * 16) * 400 + ks * 32);
#pragma unroll
            for (int j2 = 0; j2 < 2; j2++) {
                uint32_t tmp[4];
                ldsm4(tmp, bK + (uint32_t)(j2 * 16) * 400 + ks * 32);
                bb[2 * j2][0] = tmp[0]; bb[2 * j2][1] = tmp[1];
                bb[2 * j2 + 1][0] = tmp[2]; bb[2 * j2 + 1][1] = tmp[3];
            }
#pragma unroll
            for (int mi = 0; mi < 2; mi++)
#pragma unroll
                for (int j = 0; j < 4; j++)
                    mma16816(s[mi][j], a[mi], bb[j]);
        }

        if (kt >= 2 * qtile) {
#pragma unroll
            for (int mi = 0; mi < 2; mi++)
#pragma unroll
                for (int j = 0; j < 4; j++)
#pragma unroll
                    for (int r = 0; r < 4; r++) {
                        int col = kt * 64 + wn * 32 + j * 8 + (lane & 3) * 2 + (r & 1);
                        int row = q0 + wm * 32 + mi * 16 + (lane >> 2) + (r >> 1) * 8;
                        if (col > row) s[mi][j][r] = -1e30f;
                    }
        }

        float* redmax = (float*)(smem + AT_RMAX);
        float* redsum = (float*)(smem + AT_RSUM);
#pragma unroll
        for (int mi = 0; mi < 2; mi++)
#pragma unroll
            for (int ri = 0; ri < 2; ri++) {
                float mx = -1e30f;
#pragma unroll
                for (int j = 0; j < 4; j++)
                    mx = fmaxf(mx, fmaxf(s[mi][j][ri * 2], s[mi][j][ri * 2 + 1]));
                mx = fmaxf(mx, __shfl_xor_sync(0xffffffffu, mx, 1));
                mx = fmaxf(mx, __shfl_xor_sync(0xffffffffu, mx, 2));
                if ((lane & 3) == 0) {
                    int row = wm * 32 + mi * 16 + (lane >> 2) + ri * 8;
                    redmax[row * 2 + wn] = mx;
                }
            }
        __syncthreads();

        float alpha[2][2], mnow[2][2];
#pragma unroll
        for (int mi = 0; mi < 2; mi++)
#pragma unroll
            for (int ri = 0; ri < 2; ri++) {
                int row = wm * 32 + mi * 16 + (lane >> 2) + ri * 8;
                float tm = fmaxf(redmax[row * 2], redmax[row * 2 + 1]);
                float mn = fmaxf(m_st[mi][ri], tm);
                alpha[mi][ri] = __expf(m_st[mi][ri] - mn);
                m_st[mi][ri] = mn;
                mnow[mi][ri] = mn;
            }
#pragma unroll
        for (int mi = 0; mi < 2; mi++)
#pragma unroll
            for (int j = 0; j < 4; j++)
#pragma unroll
                for (int r = 0; r < 4; r++) acc_o[mi][j][r] *= alpha[mi][r >> 1];

#pragma unroll
        for (int mi = 0; mi < 2; mi++)
#pragma unroll
            for (int ri = 0; ri < 2; ri++) {
                float sum = 0.f;
                const int row = wm * 32 + mi * 16 + (lane >> 2) + ri * 8;
                const float mrow = mnow[mi][ri];
#pragma unroll
                for (int j = 0; j < 4; j++) {
                    float p0 = __expf(s[mi][j][ri * 2] - mrow);
                    float p1 = __expf(s[mi][j][ri * 2 + 1] - mrow);
                    sum += p0 + p1;
                    __nv_bfloat162 hv, lv;
                    split2(p0, p1, hv, lv);
                    uint32_t off = (uint32_t)row * 144 +
                                   (uint32_t)(wn * 32 + j * 8 + (lane & 3) * 2) * 2;
                    *(__nv_bfloat162*)(smem + AT_PH + off) = hv;
                    *(__nv_bfloat162*)(smem + AT_PL + off) = lv;
                }
                sum += __shfl_xor_sync(0xffffffffu, sum, 1);
                sum += __shfl_xor_sync(0xffffffffu, sum, 2);
                if ((lane & 3) == 0) redsum[row * 2 + wn] = sum;
            }
        __syncthreads();

#pragma unroll
        for (int mi = 0; mi < 2; mi++)
#pragma unroll
            for (int ri = 0; ri < 2; ri++) {
                int row = wm * 32 + mi * 16 + (lane >> 2) + ri * 8;
                l_st[mi][ri] = l_st[mi][ri] * alpha[mi][ri] +
                               redsum[row * 2] + redsum[row * 2 + 1];
            }

#pragma unroll
        for (int pass = 0; pass < 3; pass++) {
            const uint32_t Aoff = (pass == 1) ? AT_PL : AT_PH;
            const uint32_t plane = (pass == 2) ? 1u : 0u;
            const uint32_t aP = sb + Aoff + (uint32_t)(wm * 32 + aRow) * 144 + aColB;
            const uint32_t bV = stOff + AT_VOFF + plane * 9216 +
                                (uint32_t)(wn * 32 + bRow) * 144 + bColB;
#pragma unroll
            for (int ks = 0; ks < 4; ks++) {
                uint32_t a[2][4], bb[4][2];
#pragma unroll
                for (int mi = 0; mi < 2; mi++)
                    ldsm4(a[mi], aP + (uint32_t)(mi * 16) * 144 + ks * 32);
#pragma unroll
                for (int j2 = 0; j2 < 2; j2++) {
                    uint32_t tmp[4];
                    ldsm4(tmp, bV + (uint32_t)(j2 * 16) * 144 + ks * 32);
                    bb[2 * j2][0] = tmp[0]; bb[2 * j2][1] = tmp[1];
                    bb[2 * j2 + 1][0] = tmp[2]; bb[2 * j2 + 1][1] = tmp[3];
                }
#pragma unroll
                for (int mi = 0; mi < 2; mi++)
#pragma unroll
                    for (int j = 0; j < 4; j++)
                        mma16816(acc_o[mi][j], a[mi], bb[j]);
            }
        }
    }

    // ---- epilogue: write split-hhl bf16 rows of g_os ----
#pragma unroll
    for (int mi = 0; mi < 2; mi++)
#pragma unroll
        for (int ri = 0; ri < 2; ri++) {
            const float inv = 1.f / l_st[mi][ri];
            const int srow = q0 + wm * 32 + mi * 16 + (lane >> 2) + ri * 8;
            __nv_bfloat16* orow = Os + (size_t)(b * SS + srow) * GKP;
#pragma unroll
            for (int j = 0; j < 4; j++) {
                const int col = h * HD + wn * 32 + j * 8 + (lane & 3) * 2;
                float v0 = acc_o[mi][j][ri * 2] * inv;
                float v1 = acc_o[mi][j][ri * 2 + 1] * inv;
                __nv_bfloat162 hi, lo;
                split2(v0, v1, hi, lo);
                *(__nv_bfloat162*)(orow + col) = hi;
                *(__nv_bfloat162*)(orow + col + 2048) = hi;
                *(__nv_bfloat162*)(orow + col + 4096) = lo;
            }
        }
}

// ---------------------------------------------------------------------------
extern "C" void kernel_launch(void* const* d_in, const int* in_sizes, int n_in,
                              void* d_out, int out_size) {
    (void)in_sizes; (void)n_in; (void)out_size;
    const float* x  = (const float*)d_in[0];
    const float* wq = (const float*)d_in[1];
    const float* bq = (const float*)d_in[2];
    const float* wk = (const float*)d_in[3];
    const float* bk = (const float*)d_in[4];
    const float* wv = (const float*)d_in[5];
    const float* bv = (const float*)d_in[6];
    const float* wo = (const float*)d_in[7];
    const float* bo = (const float*)d_in[8];
    float* out = (float*)d_out;

    __nv_bfloat16 *xs, *os, *wqkvs, *wos, *q3, *k3, *vt;
    cudaGetSymbolAddress((void**)&xs,    g_xs);
    cudaGetSymbolAddress((void**)&os,    g_os);
    cudaGetSymbolAddress((void**)&wqkvs, g_wqkvs);
    cudaGetSymbolAddress((void**)&wos,   g_wos);
    cudaGetSymbolAddress((void**)&q3,    g_Q3);
    cudaGetSymbolAddress((void**)&k3,    g_K3);
    cudaGetSymbolAddress((void**)&vt,    g_Vt);

    const int M = BB * SS;  // 4096
    cudaFuncSetAttribute(gemm_mma, cudaFuncAttributeMaxDynamicSharedMemorySize,
                         GEMM_SMEM);
    cudaFuncSetAttribute(gemm_qkv, cudaFuncAttributeMaxDynamicSharedMemorySize,
                         GEMM_SMEM);
    cudaFuncSetAttribute(attn_mma, cudaFuncAttributeMaxDynamicSharedMemorySize,
                         AT_SMEM);

    // Splits: x (hhl), weights (hlh; wq/wk/wv packed into one buffer)
    split_hhl<<<(M * 2048 + 255) / 256, 256>>>(x, xs, M);
    split_hlh<<<(2048 * 2048 + 255) / 256, 256>>>(wq, wqkvs, 2048);
    split_hlh<<<(512 * 2048 + 255) / 256, 256>>>(wk, wqkvs + (size_t)2048 * GKP, 512);
    split_hlh<<<(512 * 2048 + 255) / 256, 256>>>(wv, wqkvs + (size_t)2560 * GKP, 512);
    split_hlh<<<(2048 * 2048 + 255) / 256, 256>>>(wo, wos, 2048);

    // Fused QKV projection -> attention-format outputs
    dim3 gqkv(3072 / 128, M / 128);   // (24, 32)
    gemm_qkv<<<gqkv, 128, GEMM_SMEM>>>(xs, wqkvs, bq, bk, bv, q3, k3, vt);

    // Attention (tensor cores), output fused to split-hhl
    dim3 ga(SS / 128, NH, BB);
    attn_mma<<<ga, 256, AT_SMEM>>>(q3, k3, vt, os);

    // Output projection
    dim3 gq(2048 / 128, M / 128);
    gemm_mma<<<gq, 128, GEMM_SMEM>>>(os, wos, bo, out, 2048);
}